// round 10
// baseline (speedup 1.0000x reference)
#include <cuda_runtime.h>
#include <cuda_bf16.h>

// GraphGather / segment_sum, single fused kernel:
//   out[b, :] = sum of feats[a, :] for membership[a] == b
// feats: [524288, 128] f32, membership: [524288] i32 (SORTED), out: [16384, 128] f32.
//
// R10 = R6 streamer (44.2us, DRAM 81%) with the zero-fill FUSED in:
//  - block b zeroes its owned out-slice (8 rows, one float4 store/thread),
//    __threadfence(), publishes epoch flag[b].
//  - boundary flushes (red.global.add.v4.f32) spin on flag[owner(seg)] >= epoch.
//    membership is sorted ~uniform -> owner is within a few bids of the
//    flusher; flags are set in each block's first instructions, so spins
//    effectively never engage. Waiters always wait on equal/adjacent-wave
//    bids (bid-ordered dispatch) -> deadlock-free.
//  - epoch = g_ticket / gridDim per execution: replays of the captured graph
//    each get a fresh epoch, so stale flags from a prior replay never
//    satisfy the wait (out is re-zeroed correctly every replay).

#define N_FEAT 128
#define FEAT4 (N_FEAT / 4)       // 32 float4 per row
#define ROWS_PER_WARP 32
#define TPB 256
#define MAX_BLOCKS 4096

__device__ unsigned g_ticket;               // zero-init; grows monotonically
__device__ unsigned g_flags[MAX_BLOCKS];    // epoch flags, zero-init

__device__ __forceinline__ void gg_flush(float* __restrict__ out,
                                         int seg, int lane, const float4& acc,
                                         unsigned segs_per_block, unsigned ep1) {
    // Wait until the block owning this out-slice has zeroed it (this run).
    unsigned owner = (unsigned)seg / segs_per_block;
    volatile unsigned* f = &g_flags[owner];
    while (*f < ep1) { }
    // byte offset = seg*512 + lane*16 -> 16B aligned.
    float* o = out + (size_t)seg * N_FEAT + lane * 4;
    asm volatile("red.global.add.v4.f32 [%0], {%1, %2, %3, %4};"
                 :: "l"(o), "f"(acc.x), "f"(acc.y), "f"(acc.z), "f"(acc.w)
                 : "memory");
}

__global__ __launch_bounds__(TPB)
void gg_fused_kernel(const float4* __restrict__ feats,
                     const int* __restrict__ memb,
                     float* __restrict__ out,
                     int n_atoms, int n_out4, unsigned segs_per_block) {
    const int tid = threadIdx.x;
    const int b = blockIdx.x;
    const int lane = tid & 31;
    const unsigned FULL = 0xFFFFFFFFu;

    // ---- Epoch for this execution (replay-safe flag protocol) ----
    __shared__ unsigned s_ep1;
    if (tid == 0)
        s_ep1 = (atomicAdd(&g_ticket, 1u) / gridDim.x) + 1u;
    __syncthreads();
    const unsigned ep1 = s_ep1;

    // ---- Zero this block's owned out-slice, then publish the flag ----
    {
        int zidx = b * TPB + tid;               // one float4 per thread
        if (zidx < n_out4)
            ((float4*)out)[zidx] = make_float4(0.f, 0.f, 0.f, 0.f);
    }
    __threadfence();                            // zeros visible before flag
    if (tid == 0)
        atomicExch(&g_flags[b], ep1);

    // ---- R6 streaming segment-sum ----
    const int warp_id = (b * TPB + tid) >> 5;
    const int row0 = warp_id * ROWS_PER_WARP;
    if (row0 >= n_atoms) return;

    const int last = n_atoms - 1;
    int mrow = row0 + lane;
    int mlane = memb[mrow <= last ? mrow : last];

    const int nrows = (row0 + ROWS_PER_WARP <= n_atoms) ? ROWS_PER_WARP
                                                        : (n_atoms - row0);
    const float4* base = feats + (size_t)row0 * FEAT4 + lane;

    float4 acc = make_float4(0.f, 0.f, 0.f, 0.f);
    int cur = __shfl_sync(FULL, mlane, 0);

    if (nrows == ROWS_PER_WARP) {
        #pragma unroll
        for (int bt = 0; bt < 4; ++bt) {
            // 8 independent 128-bit loads, issued back-to-back (MLP_p1 = 8).
            float4 v[8];
            #pragma unroll
            for (int i = 0; i < 8; ++i)
                v[i] = __ldcs(base + (size_t)(bt * 8 + i) * FEAT4);

            #pragma unroll
            for (int i = 0; i < 8; ++i) {
                int m = __shfl_sync(FULL, mlane, bt * 8 + i);
                if (m != cur) {            // rare: ~1 boundary / warp
                    gg_flush(out, cur, lane, acc, segs_per_block, ep1);
                    acc = make_float4(0.f, 0.f, 0.f, 0.f);
                    cur = m;
                }
                acc.x += v[i].x; acc.y += v[i].y;
                acc.z += v[i].z; acc.w += v[i].w;
            }
        }
    } else {
        for (int i = 0; i < nrows; ++i) {
            float4 v = __ldcs(base + (size_t)i * FEAT4);
            int m = __shfl_sync(FULL, mlane, i);
            if (m != cur) {
                gg_flush(out, cur, lane, acc, segs_per_block, ep1);
                acc = make_float4(0.f, 0.f, 0.f, 0.f);
                cur = m;
            }
            acc.x += v.x; acc.y += v.y; acc.z += v.z; acc.w += v.w;
        }
    }

    gg_flush(out, cur, lane, acc, segs_per_block, ep1);
}

extern "C" void kernel_launch(void* const* d_in, const int* in_sizes, int n_in,
                              void* d_out, int out_size) {
    const float4* feats = (const float4*)d_in[0];
    const int* memb = (const int*)d_in[1];
    float* out = (float*)d_out;

    const int n_atoms = in_sizes[1];          // 524288
    const int n_out4 = out_size / 4;          // 524288 float4
    const int n_segs = out_size / N_FEAT;     // 16384

    // Blocks sized so both roles are covered exactly:
    //  - streaming: n_atoms / (32 rows * 8 warps) = 2048 blocks
    //  - zeroing:   n_out4 / 256 = 2048 blocks
    int blocks_stream = (n_atoms + ROWS_PER_WARP * (TPB / 32) - 1) /
                        (ROWS_PER_WARP * (TPB / 32));
    int blocks_zero = (n_out4 + TPB - 1) / TPB;
    int blocks = blocks_stream > blocks_zero ? blocks_stream : blocks_zero;
    if (blocks > MAX_BLOCKS) blocks = MAX_BLOCKS;   // sizes are fixed: 2048

    unsigned segs_per_block = (unsigned)((n_segs + blocks - 1) / blocks);  // 8

    gg_fused_kernel<<<blocks, TPB>>>(feats, memb, out,
                                     n_atoms, n_out4, segs_per_block);
}